// round 1
// baseline (speedup 1.0000x reference)
#include <cuda_runtime.h>
#include <cstdint>

// CorticalSheet fixed-degree SpMM:
//   out[n, b] = sum_k values[n, k] * x[indices[n, k], b] + bias[n]
// N = 1e6, K = 32, B = 8.
//
// Scheme: quarter-warp per neuron. Each warp handles 4 neurons.
//   lane = g*8 + b, g in [0,4) local neuron, b in [0,8) output column.
// Per synapse k: the 8 lanes of a group read x[idx*8 + b] -> one 32B sector,
// one L1 wavefront per (n,k) gather (the hardware floor). No reduction shuffles;
// each lane accumulates its own column.

static constexpr int K_SYN = 32;
static constexpr int B_COL = 8;

__global__ __launch_bounds__(256)
void cortical_spmm_kernel(const float* __restrict__ x,
                          const float* __restrict__ values,
                          const float* __restrict__ bias,
                          const int*   __restrict__ indices,
                          float* __restrict__ out,
                          int N) {
    const int tid  = blockIdx.x * blockDim.x + threadIdx.x;
    const int warp = tid >> 5;
    const int lane = threadIdx.x & 31;
    const int b    = lane & 7;        // output column owned by this lane
    const int gbase = lane & 24;      // first lane of this 8-lane group

    const long n = (long)warp * 4 + (lane >> 3);   // neuron for this group
    const bool active = (n < N);

    // Preload this group's 32 indices + 32 values, 4 per lane (chunk = b).
    // Addresses: flat = n*32 + b*4 -> warp covers 512B contiguous, 16B/lane.
    int4   idx4 = make_int4(0, 0, 0, 0);
    float4 val4 = make_float4(0.f, 0.f, 0.f, 0.f);
    if (active) {
        const size_t base = (size_t)n * K_SYN + (size_t)b * 4;
        idx4 = *reinterpret_cast<const int4*>(indices + base);
        val4 = *reinterpret_cast<const float4*>(values + base);
    }

    const float* __restrict__ xb = x + b;

    float a0 = 0.f, a1 = 0.f, a2 = 0.f, a3 = 0.f;

    #pragma unroll
    for (int k4 = 0; k4 < 8; ++k4) {
        const int src = gbase + k4;   // lane holding chunk k4 of this neuron
        const int   i0 = __shfl_sync(0xffffffffu, idx4.x, src);
        const int   i1 = __shfl_sync(0xffffffffu, idx4.y, src);
        const int   i2 = __shfl_sync(0xffffffffu, idx4.z, src);
        const int   i3 = __shfl_sync(0xffffffffu, idx4.w, src);
        const float v0 = __shfl_sync(0xffffffffu, val4.x, src);
        const float v1 = __shfl_sync(0xffffffffu, val4.y, src);
        const float v2 = __shfl_sync(0xffffffffu, val4.z, src);
        const float v3 = __shfl_sync(0xffffffffu, val4.w, src);

        // Inactive tail lanes have idx=0, v=0: loads x[b] (valid), adds 0.
        a0 = fmaf(v0, __ldg(xb + (size_t)i0 * B_COL), a0);
        a1 = fmaf(v1, __ldg(xb + (size_t)i1 * B_COL), a1);
        a2 = fmaf(v2, __ldg(xb + (size_t)i2 * B_COL), a2);
        a3 = fmaf(v3, __ldg(xb + (size_t)i3 * B_COL), a3);
    }

    if (active) {
        const float acc = (a0 + a1) + (a2 + a3);
        out[(size_t)n * B_COL + b] = acc + __ldg(bias + n);
    }
}

extern "C" void kernel_launch(void* const* d_in, const int* in_sizes, int n_in,
                              void* d_out, int out_size) {
    const float* x       = (const float*)d_in[0];
    const float* values  = (const float*)d_in[1];
    const float* bias    = (const float*)d_in[2];
    const int*   indices = (const int*)d_in[3];
    float* out = (float*)d_out;

    const int N = in_sizes[2];            // bias has one element per neuron

    // 4 neurons per warp, 8 warps per block -> 32 neurons per 256-thread block.
    const int neurons_per_block = 32;
    const int grid = (N + neurons_per_block - 1) / neurons_per_block;

    cortical_spmm_kernel<<<grid, 256>>>(x, values, bias, indices, out, N);
}